// round 14
// baseline (speedup 1.0000x reference)
#include <cuda_runtime.h>
#include <cuda_fp16.h>
#include <math.h>

#define BATCH 2
#define SEQ 2048
#define DMODEL 1024
#define NHEAD 16
#define DHEAD 64
#define MROWS (BATCH*SEQ)   /* 4096 */

// Scratch (allocation-free) — all fp16
__device__ __half g_qh[MROWS*DMODEL];
__device__ __half g_kh[MROWS*DMODEL];
__device__ __half g_vh[MROWS*DMODEL];
__device__ __half g_Wqh[DMODEL*DMODEL];
__device__ __half g_Wkh[DMODEL*DMODEL];
__device__ __half g_Wvh[DMODEL*DMODEL];
__device__ __half g_Woh[DMODEL*DMODEL];
__device__ __half g_qw[MROWS*DMODEL];
__device__ __half g_kw[MROWS*DMODEL];
__device__ __half g_vw[MROWS*DMODEL];
__device__ __half g_att[MROWS*DMODEL];

// ---------------------------------------------------------------------------
// Helpers
// ---------------------------------------------------------------------------
__device__ __forceinline__ float ex2(float x) {
    float r;
    asm("ex2.approx.f32 %0, %1;" : "=f"(r) : "f"(x));
    return r;
}

__device__ __forceinline__ void mma16(float* d, const unsigned* a,
                                      unsigned b0, unsigned b1) {
    asm volatile(
        "mma.sync.aligned.m16n8k16.row.col.f32.f16.f16.f32 "
        "{%0,%1,%2,%3}, {%4,%5,%6,%7}, {%8,%9}, {%0,%1,%2,%3};"
        : "+f"(d[0]), "+f"(d[1]), "+f"(d[2]), "+f"(d[3])
        : "r"(a[0]), "r"(a[1]), "r"(a[2]), "r"(a[3]), "r"(b0), "r"(b1));
}

__device__ __forceinline__ void ldsm4(unsigned& r0, unsigned& r1,
                                      unsigned& r2, unsigned& r3, unsigned a) {
    asm volatile("ldmatrix.sync.aligned.m8n8.x4.shared.b16 {%0,%1,%2,%3}, [%4];"
        : "=r"(r0), "=r"(r1), "=r"(r2), "=r"(r3) : "r"(a));
}
__device__ __forceinline__ void ldsm4t(unsigned& r0, unsigned& r1,
                                       unsigned& r2, unsigned& r3, unsigned a) {
    asm volatile("ldmatrix.sync.aligned.m8n8.x4.trans.shared.b16 {%0,%1,%2,%3}, [%4];"
        : "=r"(r0), "=r"(r1), "=r"(r2), "=r"(r3) : "r"(a));
}

__device__ __forceinline__ void cp16(const void* smem_dst, const void* gsrc) {
    unsigned d = (unsigned)__cvta_generic_to_shared(smem_dst);
    asm volatile("cp.async.cg.shared.global [%0], [%1], 16;" :: "r"(d), "l"(gsrc));
}
#define CP_COMMIT asm volatile("cp.async.commit_group;")
#define CP_WAIT0  asm volatile("cp.async.wait_group 0;")
#define CP_WAIT1  asm volatile("cp.async.wait_group 1;")

// ---------------------------------------------------------------------------
// Pre-round: f32 -> fp16 copies. blockIdx.y selects tensor.
// ---------------------------------------------------------------------------
__global__ __launch_bounds__(256) void pre_round(
    const float* __restrict__ q, const float* __restrict__ k,
    const float* __restrict__ v,
    const float* __restrict__ Wq, const float* __restrict__ Wk,
    const float* __restrict__ Wv, const float* __restrict__ Wo)
{
    const float* src; __half* dst; int n;
    switch (blockIdx.y) {
        case 0: src = q;  dst = g_qh;  n = MROWS*DMODEL;  break;
        case 1: src = k;  dst = g_kh;  n = MROWS*DMODEL;  break;
        case 2: src = v;  dst = g_vh;  n = MROWS*DMODEL;  break;
        case 3: src = Wq; dst = g_Wqh; n = DMODEL*DMODEL; break;
        case 4: src = Wk; dst = g_Wkh; n = DMODEL*DMODEL; break;
        case 5: src = Wv; dst = g_Wvh; n = DMODEL*DMODEL; break;
        default: src = Wo; dst = g_Woh; n = DMODEL*DMODEL; break;
    }
    const int idx = (blockIdx.x * 256 + threadIdx.x) * 8;
    if (idx < n) {
        float4 a = *(const float4*)(src + idx);
        float4 b = *(const float4*)(src + idx + 4);
        __half2 h[4];
        h[0] = __floats2half2_rn(a.x, a.y);
        h[1] = __floats2half2_rn(a.z, a.w);
        h[2] = __floats2half2_rn(b.x, b.y);
        h[3] = __floats2half2_rn(b.z, b.w);
        *(uint4*)(dst + idx) = *(uint4*)h;
    }
}

// ---------------------------------------------------------------------------
// GEMM: C[m,n] = sum_k A[m,k]*W[n,k] + bias[n], fp16 operands, f32 accum.
// CTA 128x128, BK=64 double-buffered cp.async, 4 warps (2x2) of 64x64.
// Pitch 72 halfs (144B) -> conflict-free LDSM.
// ---------------------------------------------------------------------------
#define APITCH 72                 /* halfs */
#define ABYTES (128*APITCH*2)     /* 18432 per buffer */

template<int OUT_HALF>
__device__ __forceinline__ void gemm_body(
    const __half* __restrict__ A, const __half* __restrict__ W,
    const float* __restrict__ bias, float* __restrict__ Cf,
    __half* __restrict__ Ch, char* smem)
{
    __half* Asm = (__half*)smem;                  // [2][128*APITCH]
    __half* Wsm = (__half*)(smem + 2*ABYTES);
    const unsigned sA = (unsigned)__cvta_generic_to_shared(Asm);
    const unsigned sW = (unsigned)__cvta_generic_to_shared(Wsm);

    const int tid  = threadIdx.x;
    const int lane = tid & 31;
    const int wid  = tid >> 5;           // 0..3
    const int bm = blockIdx.y * 128;
    const int bn = blockIdx.x * 128;
    const int wm = (wid & 1) * 64;
    const int wn = (wid >> 1) * 64;

    const __half* Ag = A + (size_t)bm * DMODEL;
    const __half* Wg = W + (size_t)bn * DMODEL;

    float acc[4][8][4];
    #pragma unroll
    for (int mf = 0; mf < 4; mf++)
        #pragma unroll
        for (int nf = 0; nf < 8; nf++)
            #pragma unroll
            for (int e = 0; e < 4; e++) acc[mf][nf][e] = 0.0f;

    auto stage = [&](int buf, int k0) {
        #pragma unroll
        for (int i = 0; i < 8; i++) {
            const int idx = i*128 + tid;
            const int row = idx >> 3;
            const int c   = (idx & 7) * 8;
            cp16(Asm + buf*(128*APITCH) + row*APITCH + c,
                 Ag + (size_t)row*DMODEL + k0 + c);
            cp16(Wsm + buf*(128*APITCH) + row*APITCH + c,
                 Wg + (size_t)row*DMODEL + k0 + c);
        }
        CP_COMMIT;
    };

    stage(0, 0);

    // ldmatrix lane addressing (g = lane>>3 selects sub-matrix)
    const int g = lane >> 3, r = lane & 7;
    const unsigned aBase = sA + (unsigned)((wm + (g&1)*8 + r) * 144 + (g>>1)*16);
    const unsigned wBase = sW + (unsigned)((wn + (g&1)*8 + r) * 144 + (g>>1)*16);

    const int ntiles = DMODEL / 64;      // 16
    for (int kt = 0; kt < ntiles; kt++) {
        const int cur = kt & 1;
        if (kt + 1 < ntiles) {
            stage(cur ^ 1, (kt + 1) * 64);
            CP_WAIT1;
        } else {
            CP_WAIT0;
        }
        __syncthreads();

        const unsigned ab = aBase + cur*ABYTES;
        const unsigned wb = wBase + cur*ABYTES;
        #pragma unroll
        for (int s = 0; s < 4; s++) {                 // 4 k16-steps
            unsigned af[4][4];
            #pragma unroll
            for (int mf = 0; mf < 4; mf++)
                ldsm4(af[mf][0], af[mf][1], af[mf][2], af[mf][3],
                      ab + mf*16*144 + s*32);
            #pragma unroll
            for (int nf2 = 0; nf2 < 4; nf2++) {
                unsigned b0, b1, b2, b3;
                ldsm4(b0, b1, b2, b3, wb + nf2*16*144 + s*32);
                #pragma unroll
                for (int mf = 0; mf < 4; mf++) {
                    mma16(acc[mf][nf2*2],   af[mf], b0, b2);
                    mma16(acc[mf][nf2*2+1], af[mf], b1, b3);
                }
            }
        }
        __syncthreads();
    }

    // Epilogue
    #pragma unroll
    for (int mf = 0; mf < 4; mf++) {
        const int m0 = bm + wm + mf*16 + (lane>>2);
        #pragma unroll
        for (int nf = 0; nf < 8; nf++) {
            const int n0 = bn + wn + nf*8 + 2*(lane&3);
            const float2 bv = *(const float2*)(bias + n0);
            const float r00 = acc[mf][nf][0] + bv.x, r01 = acc[mf][nf][1] + bv.y;
            const float r10 = acc[mf][nf][2] + bv.x, r11 = acc[mf][nf][3] + bv.y;
            if (OUT_HALF) {
                *(__half2*)(Ch + (size_t)m0 * DMODEL + n0) =
                    __floats2half2_rn(r00, r01);
                *(__half2*)(Ch + (size_t)(m0+8) * DMODEL + n0) =
                    __floats2half2_rn(r10, r11);
            } else {
                *(float2*)(Cf + (size_t)m0 * DMODEL + n0)     = make_float2(r00, r01);
                *(float2*)(Cf + (size_t)(m0+8) * DMODEL + n0) = make_float2(r10, r11);
            }
        }
    }
}

__global__ __launch_bounds__(128, 2) void gemm_out(
    const __half* __restrict__ A, const __half* __restrict__ W,
    const float* __restrict__ bias, float* __restrict__ C)
{
    extern __shared__ __align__(16) char smg[];
    gemm_body<0>(A, W, bias, C, nullptr, smg);
}

__global__ __launch_bounds__(128, 2) void gemm_qkv(
    const float* __restrict__ bq, const float* __restrict__ bk,
    const float* __restrict__ bv)
{
    extern __shared__ __align__(16) char smg[];
    const __half* A; const __half* W; const float* bias; __half* C;
    if (blockIdx.z == 0)      { A = g_qh; W = g_Wqh; bias = bq; C = g_qw; }
    else if (blockIdx.z == 1) { A = g_kh; W = g_Wkh; bias = bk; C = g_kw; }
    else                      { A = g_vh; W = g_Wvh; bias = bv; C = g_vw; }
    gemm_body<1>(A, W, bias, nullptr, C, smg);
}

// ---------------------------------------------------------------------------
// Flash attention, fp16 mma + ldmatrix, FA2-style: P stays in registers
// (A-fragment of PV mma == packed S accumulator fragments; no smem round
// trip). K/V double-buffered cp.async. scale = 1/32 in the exponent.
// ---------------------------------------------------------------------------
#define FPH 72    /* halfs */
#define KVB (64*FPH*2)   /* 9216 bytes per K or V buffer */

__global__ __launch_bounds__(256, 2) void flash_mma(
    const __half* __restrict__ Q, const __half* __restrict__ K,
    const __half* __restrict__ V, __half* __restrict__ O)
{
    extern __shared__ __align__(16) char smf[];
    __half* Qs = (__half*)smf;              // [128][FPH]
    __half* Ks = Qs + 128*FPH;              // [2][64][FPH]
    __half* Vs = Ks + 2*64*FPH;             // [2][64][FPH] row-major (j, d)
    const unsigned sQ = (unsigned)__cvta_generic_to_shared(Qs);
    const unsigned sK = (unsigned)__cvta_generic_to_shared(Ks);
    const unsigned sV = (unsigned)__cvta_generic_to_shared(Vs);

    const int qt = gridDim.x - 1 - blockIdx.x;   // big tiles first
    const int h  = blockIdx.y;
    const int b  = blockIdx.z;
    const int tid  = threadIdx.x;
    const int lane = tid & 31;
    const int wid  = tid >> 5;
    const int qBase = qt * 128;

    const __half* Qg  = Q + ((size_t)b * SEQ + qBase) * DMODEL + h * DHEAD;
    const __half* Kg0 = K + ((size_t)b * SEQ) * DMODEL + h * DHEAD;
    const __half* Vg0 = V + ((size_t)b * SEQ) * DMODEL + h * DHEAD;

    // Stage Q: 128 rows x 64 halfs = 1024 16B-chunks, 4 per thread
    #pragma unroll
    for (int i = 0; i < 4; i++) {
        const int idx = i*256 + tid;
        const int row = idx >> 3;
        const int c   = (idx & 7) * 8;
        cp16(Qs + row*FPH + c, Qg + (size_t)row*DMODEL + c);
    }

    auto stageKV = [&](int kBase, int buf) {
        #pragma unroll
        for (int i = 0; i < 2; i++) {
            const int idx = i*256 + tid;
            const int row = idx >> 3;
            const int c   = (idx & 7) * 8;
            cp16(Ks + buf*(64*FPH) + row*FPH + c,
                 Kg0 + (size_t)(kBase + row)*DMODEL + c);
            cp16(Vs + buf*(64*FPH) + row*FPH + c,
                 Vg0 + (size_t)(kBase + row)*DMODEL + c);
        }
        CP_COMMIT;
    };
    stageKV(0, 0);

    const int r0  = (wid << 4) + (lane >> 2);
    const int qi0 = qBase + r0;
    const int qi1 = qi0 + 8;

    // ldmatrix addressing
    const int g = lane >> 3, r = lane & 7;
    const unsigned qRow = sQ + (unsigned)((wid*16 + (g&1)*8 + r) * 144 + (g>>1)*16);
    const unsigned kRow = sK + (unsigned)(((g&1)*8 + r) * 144 + (g>>1)*16);
    const unsigned vRow = sV + (unsigned)(((g>>1)*8 + r) * 144 + (g&1)*16);

    float m0 = -1e30f, m1 = -1e30f, l0 = 0.0f, l1 = 0.0f;
    float o[8][4];
    #pragma unroll
    for (int nf = 0; nf < 8; nf++)
        #pragma unroll
        for (int e = 0; e < 4; e++) o[nf][e] = 0.0f;

    const float c2 = 0.03125f * 1.4426950408889634f;  // scale * log2(e)

    const int ktMax = 2*qt + 1;
    for (int kt = 0; kt <= ktMax; kt++) {
        const int cur = kt & 1;
        CP_WAIT0;                // K/V(kt) [+Q on kt=0] landed
        __syncthreads();         // all threads past iter kt-1 reads

        // Prefetch next K/V tile — overlaps with this tile's compute
        if (kt < ktMax) stageKV((kt + 1) * 64, cur ^ 1);

        const unsigned kb = kRow + cur*KVB;
        const unsigned vb = vRow + cur*KVB;
        const int kBase = kt * 64;

        // S = Q @ K^T (unscaled)
        float s[8][4];
        #pragma unroll
        for (int nf = 0; nf < 8; nf++)
            #pragma unroll
            for (int e = 0; e < 4; e++) s[nf][e] = 0.0f;

        #pragma unroll
        for (int ks = 0; ks < 4; ks++) {          // k16 steps over d=64
            unsigned a[4];
            ldsm4(a[0], a[1], a[2], a[3], qRow + ks*32);
            #pragma unroll
            for (int nf2 = 0; nf2 < 4; nf2++) {
                unsigned b0, b1, b2, b3;
                ldsm4(b0, b1, b2, b3, kb + nf2*16*144 + ks*32);
                mma16(s[nf2*2],   a, b0, b2);
                mma16(s[nf2*2+1], a, b1, b3);
            }
        }

        // Mask + online softmax
        const bool needMask = (kt >= 2*qt);
        float mt0 = -1e30f, mt1 = -1e30f;
        #pragma unroll
        for (int nf = 0; nf < 8; nf++) {
            #pragma unroll
            for (int e = 0; e < 2; e++) {
                if (needMask) {
                    const int kj = kBase + nf*8 + 2*(lane&3) + e;
                    if (kj > qi0) s[nf][e]   = -1e30f;
                    if (kj > qi1) s[nf][2+e] = -1e30f;
                }
                mt0 = fmaxf(mt0, s[nf][e]);
                mt1 = fmaxf(mt1, s[nf][2+e]);
            }
        }
        mt0 = fmaxf(mt0, __shfl_xor_sync(0xffffffffu, mt0, 1));
        mt0 = fmaxf(mt0, __shfl_xor_sync(0xffffffffu, mt0, 2));
        mt1 = fmaxf(mt1, __shfl_xor_sync(0xffffffffu, mt1, 1));
        mt1 = fmaxf(mt1, __shfl_xor_sync(0xffffffffu, mt1, 2));

        const float mn0 = fmaxf(m0, mt0);
        const float mn1 = fmaxf(m1, mt1);
        const float alpha0 = ex2((m0 - mn0) * c2);
        const float alpha1 = ex2((m1 - mn1) * c2);
        m0 = mn0; m1 = mn1;

        float ls0 = 0.0f, ls1 = 0.0f;
        #pragma unroll
        for (int nf = 0; nf < 8; nf++) {
            #pragma unroll
            for (int e = 0; e < 2; e++) {
                const float p0 = ex2((s[nf][e]   - mn0) * c2);
                const float p1 = ex2((s[nf][2+e] - mn1) * c2);
                s[nf][e]   = p0;
                s[nf][2+e] = p1;
                ls0 += p0; ls1 += p1;
            }
        }
        ls0 += __shfl_xor_sync(0xffffffffu, ls0, 1);
        ls0 += __shfl_xor_sync(0xffffffffu, ls0, 2);
        ls1 += __shfl_xor_sync(0xffffffffu, ls1, 1);
        ls1 += __shfl_xor_sync(0xffffffffu, ls1, 2);
        l0 = l0*alpha0 + ls0;
        l1 = l1*alpha1 + ls1;

        #pragma unroll
        for (int nf = 0; nf < 8; nf++) {
            o[nf][0] *= alpha0; o[nf][1] *= alpha0;
            o[nf][2] *= alpha1; o[nf][3] *= alpha1;
        }

        // O += P @ V — FA2 identity: P A-fragments are the packed S
        // accumulator fragments (two adjacent n8 tiles per k16 step).
        #pragma unroll
        for (int ks = 0; ks < 4; ks++) {          // k16 steps over j=64
            unsigned a[4];
            __half2 h0 = __floats2half2_rn(s[2*ks][0],   s[2*ks][1]);
            __half2 h1 = __floats2half2_rn(s[2*ks][2],   s[2*ks][3]);
            __half2 h2 = __floats2half2_rn(s[2*ks+1][0], s[2*ks+1][1]);
            __half2 h3 = __floats2half2_rn(s[2*ks+1][2], s[2*ks+1][3]);
            a[0] = *(unsigned*)&h0;
            a[1] = *(unsigned*)&h1;
            a[2] = *(unsigned*)&h2;
            a[3] = *(unsigned*)&h3;
            #pragma unroll
            for (int nf2 = 0; nf2 < 4; nf2++) {
                unsigned b0, b1, b2, b3;
                ldsm4t(b0, b1, b2, b3, vb + ks*16*144 + nf2*32);
                mma16(o[nf2*2],   a, b0, b2);
                mma16(o[nf2*2+1], a, b1, b3);
            }
        }
    }

    // Normalize + write fp16
    const float inv0 = 1.0f / l0;
    const float inv1 = 1.0f / l1;
    __half* Ob = O + (size_t)b * SEQ * DMODEL + (size_t)h * DHEAD;
    #pragma unroll
    for (int nf = 0; nf < 8; nf++) {
        const int n = nf*8 + 2*(lane&3);
        *(__half2*)(Ob + (size_t)qi0 * DMODEL + n) =
            __floats2half2_rn(o[nf][0]*inv0, o[nf][1]*inv0);
        *(__half2*)(Ob + (size_t)qi1 * DMODEL + n) =
            __floats2half2_rn(o[nf][2]*inv1, o[nf][3]*inv1);
    }
}

// ---------------------------------------------------------------------------
extern "C" void kernel_launch(void* const* d_in, const int* in_sizes, int n_in,
                              void* d_out, int out_size)
{
    const float* q  = (const float*)d_in[0];
    const float* k  = (const float*)d_in[1];
    const float* v  = (const float*)d_in[2];
    const float* Wq = (const float*)d_in[3];
    const float* bq = (const float*)d_in[4];
    const float* Wk = (const float*)d_in[5];
    const float* bk = (const float*)d_in[6];
    const float* Wv = (const float*)d_in[7];
    const float* bv = (const float*)d_in[8];
    const float* Wo = (const float*)d_in[9];
    const float* bo = (const float*)d_in[10];
    float* out = (float*)d_out;

    __half *qw, *kw, *vw, *att, *Woh;
    cudaGetSymbolAddress((void**)&qw,  g_qw);
    cudaGetSymbolAddress((void**)&kw,  g_kw);
    cudaGetSymbolAddress((void**)&vw,  g_vw);
    cudaGetSymbolAddress((void**)&att, g_att);
    cudaGetSymbolAddress((void**)&Woh, g_Woh);

    const int smemGemm  = 4 * ABYTES;                          // 73728
    const int smemFlash = (128*FPH + 2*64*FPH + 2*64*FPH) * 2; // 55296
    cudaFuncSetAttribute(gemm_qkv,
                         cudaFuncAttributeMaxDynamicSharedMemorySize, smemGemm);
    cudaFuncSetAttribute(gemm_out,
                         cudaFuncAttributeMaxDynamicSharedMemorySize, smemGemm);
    cudaFuncSetAttribute(flash_mma,
                         cudaFuncAttributeMaxDynamicSharedMemorySize, smemFlash);

    // 1) fp16 pre-round of inputs + weights
    pre_round<<<dim3(MROWS*DMODEL/(256*8), 7), 256>>>(q, k, v, Wq, Wk, Wv, Wo);

    // 2) fused QKV projections (fp16 out)
    dim3 gQKV(DMODEL/128, MROWS/128, 3);
    gemm_qkv<<<gQKV, 128, smemGemm>>>(bq, bk, bv);

    // 3) causal flash attention (fp16 out)
    flash_mma<<<dim3(SEQ/128, NHEAD, BATCH), 256, smemFlash>>>(qw, kw, vw, att);

    // 4) output projection (f32 out)
    dim3 gGemm(DMODEL/128, MROWS/128);
    gemm_out<<<gGemm, 128, smemGemm>>>(att, Woh, bo, out);
}

// round 15
// speedup vs baseline: 1.0024x; 1.0024x over previous
#include <cuda_runtime.h>
#include <cuda_fp16.h>
#include <math.h>

#define BATCH 2
#define SEQ 2048
#define DMODEL 1024
#define NHEAD 16
#define DHEAD 64
#define MROWS (BATCH*SEQ)   /* 4096 */

// Scratch (allocation-free) — all fp16
__device__ __half g_qh[MROWS*DMODEL];
__device__ __half g_kh[MROWS*DMODEL];
__device__ __half g_vh[MROWS*DMODEL];
__device__ __half g_Wqh[DMODEL*DMODEL];
__device__ __half g_Wkh[DMODEL*DMODEL];
__device__ __half g_Wvh[DMODEL*DMODEL];
__device__ __half g_Woh[DMODEL*DMODEL];
__device__ __half g_qw[MROWS*DMODEL];
__device__ __half g_kw[MROWS*DMODEL];
__device__ __half g_vw[MROWS*DMODEL];
__device__ __half g_att[MROWS*DMODEL];

// ---------------------------------------------------------------------------
// Helpers
// ---------------------------------------------------------------------------
__device__ __forceinline__ float ex2(float x) {
    float r;
    asm("ex2.approx.f32 %0, %1;" : "=f"(r) : "f"(x));
    return r;
}

__device__ __forceinline__ void mma16(float* d, const unsigned* a,
                                      unsigned b0, unsigned b1) {
    asm volatile(
        "mma.sync.aligned.m16n8k16.row.col.f32.f16.f16.f32 "
        "{%0,%1,%2,%3}, {%4,%5,%6,%7}, {%8,%9}, {%0,%1,%2,%3};"
        : "+f"(d[0]), "+f"(d[1]), "+f"(d[2]), "+f"(d[3])
        : "r"(a[0]), "r"(a[1]), "r"(a[2]), "r"(a[3]), "r"(b0), "r"(b1));
}

__device__ __forceinline__ void ldsm4(unsigned& r0, unsigned& r1,
                                      unsigned& r2, unsigned& r3, unsigned a) {
    asm volatile("ldmatrix.sync.aligned.m8n8.x4.shared.b16 {%0,%1,%2,%3}, [%4];"
        : "=r"(r0), "=r"(r1), "=r"(r2), "=r"(r3) : "r"(a));
}
__device__ __forceinline__ void ldsm4t(unsigned& r0, unsigned& r1,
                                       unsigned& r2, unsigned& r3, unsigned a) {
    asm volatile("ldmatrix.sync.aligned.m8n8.x4.trans.shared.b16 {%0,%1,%2,%3}, [%4];"
        : "=r"(r0), "=r"(r1), "=r"(r2), "=r"(r3) : "r"(a));
}

__device__ __forceinline__ void cp16(const void* smem_dst, const void* gsrc) {
    unsigned d = (unsigned)__cvta_generic_to_shared(smem_dst);
    asm volatile("cp.async.cg.shared.global [%0], [%1], 16;" :: "r"(d), "l"(gsrc));
}
#define CP_COMMIT asm volatile("cp.async.commit_group;")
#define CP_WAIT0  asm volatile("cp.async.wait_group 0;")
#define CP_WAIT1  asm volatile("cp.async.wait_group 1;")

// ---------------------------------------------------------------------------
// Pre-round: f32 -> fp16 copies. blockIdx.y selects tensor.
// ---------------------------------------------------------------------------
__global__ __launch_bounds__(256) void pre_round(
    const float* __restrict__ q, const float* __restrict__ k,
    const float* __restrict__ v,
    const float* __restrict__ Wq, const float* __restrict__ Wk,
    const float* __restrict__ Wv, const float* __restrict__ Wo)
{
    const float* src; __half* dst; int n;
    switch (blockIdx.y) {
        case 0: src = q;  dst = g_qh;  n = MROWS*DMODEL;  break;
        case 1: src = k;  dst = g_kh;  n = MROWS*DMODEL;  break;
        case 2: src = v;  dst = g_vh;  n = MROWS*DMODEL;  break;
        case 3: src = Wq; dst = g_Wqh; n = DMODEL*DMODEL; break;
        case 4: src = Wk; dst = g_Wkh; n = DMODEL*DMODEL; break;
        case 5: src = Wv; dst = g_Wvh; n = DMODEL*DMODEL; break;
        default: src = Wo; dst = g_Woh; n = DMODEL*DMODEL; break;
    }
    const int idx = (blockIdx.x * 256 + threadIdx.x) * 8;
    if (idx < n) {
        float4 a = *(const float4*)(src + idx);
        float4 b = *(const float4*)(src + idx + 4);
        __half2 h[4];
        h[0] = __floats2half2_rn(a.x, a.y);
        h[1] = __floats2half2_rn(a.z, a.w);
        h[2] = __floats2half2_rn(b.x, b.y);
        h[3] = __floats2half2_rn(b.z, b.w);
        *(uint4*)(dst + idx) = *(uint4*)h;
    }
}

// ---------------------------------------------------------------------------
// GEMM: C[m,n] = sum_k A[m,k]*W[n,k] + bias[n], fp16 operands, f32 accum.
// CTA 128x128, BK=64 double-buffered cp.async, 4 warps (2x2) of 64x64.
// Pitch 72 halfs (144B) -> conflict-free LDSM.
// ---------------------------------------------------------------------------
#define APITCH 72                 /* halfs */
#define ABYTES (128*APITCH*2)     /* 18432 per buffer */

template<int OUT_HALF>
__device__ __forceinline__ void gemm_body(
    const __half* __restrict__ A, const __half* __restrict__ W,
    const float* __restrict__ bias, float* __restrict__ Cf,
    __half* __restrict__ Ch, char* smem)
{
    __half* Asm = (__half*)smem;                  // [2][128*APITCH]
    __half* Wsm = (__half*)(smem + 2*ABYTES);
    const unsigned sA = (unsigned)__cvta_generic_to_shared(Asm);
    const unsigned sW = (unsigned)__cvta_generic_to_shared(Wsm);

    const int tid  = threadIdx.x;
    const int lane = tid & 31;
    const int wid  = tid >> 5;           // 0..3
    const int bm = blockIdx.y * 128;
    const int bn = blockIdx.x * 128;
    const int wm = (wid & 1) * 64;
    const int wn = (wid >> 1) * 64;

    const __half* Ag = A + (size_t)bm * DMODEL;
    const __half* Wg = W + (size_t)bn * DMODEL;

    float acc[4][8][4];
    #pragma unroll
    for (int mf = 0; mf < 4; mf++)
        #pragma unroll
        for (int nf = 0; nf < 8; nf++)
            #pragma unroll
            for (int e = 0; e < 4; e++) acc[mf][nf][e] = 0.0f;

    auto stage = [&](int buf, int k0) {
        #pragma unroll
        for (int i = 0; i < 8; i++) {
            const int idx = i*128 + tid;
            const int row = idx >> 3;
            const int c   = (idx & 7) * 8;
            cp16(Asm + buf*(128*APITCH) + row*APITCH + c,
                 Ag + (size_t)row*DMODEL + k0 + c);
            cp16(Wsm + buf*(128*APITCH) + row*APITCH + c,
                 Wg + (size_t)row*DMODEL + k0 + c);
        }
        CP_COMMIT;
    };

    stage(0, 0);

    // ldmatrix lane addressing (g = lane>>3 selects sub-matrix)
    const int g = lane >> 3, r = lane & 7;
    const unsigned aBase = sA + (unsigned)((wm + (g&1)*8 + r) * 144 + (g>>1)*16);
    const unsigned wBase = sW + (unsigned)((wn + (g&1)*8 + r) * 144 + (g>>1)*16);

    const int ntiles = DMODEL / 64;      // 16
    for (int kt = 0; kt < ntiles; kt++) {
        const int cur = kt & 1;
        if (kt + 1 < ntiles) {
            stage(cur ^ 1, (kt + 1) * 64);
            CP_WAIT1;
        } else {
            CP_WAIT0;
        }
        __syncthreads();

        const unsigned ab = aBase + cur*ABYTES;
        const unsigned wb = wBase + cur*ABYTES;
        #pragma unroll
        for (int s = 0; s < 4; s++) {                 // 4 k16-steps
            unsigned af[4][4];
            #pragma unroll
            for (int mf = 0; mf < 4; mf++)
                ldsm4(af[mf][0], af[mf][1], af[mf][2], af[mf][3],
                      ab + mf*16*144 + s*32);
            #pragma unroll
            for (int nf2 = 0; nf2 < 4; nf2++) {
                unsigned b0, b1, b2, b3;
                ldsm4(b0, b1, b2, b3, wb + nf2*16*144 + s*32);
                #pragma unroll
                for (int mf = 0; mf < 4; mf++) {
                    mma16(acc[mf][nf2*2],   af[mf], b0, b2);
                    mma16(acc[mf][nf2*2+1], af[mf], b1, b3);
                }
            }
        }
        __syncthreads();
    }

    // Epilogue
    #pragma unroll
    for (int mf = 0; mf < 4; mf++) {
        const int m0 = bm + wm + mf*16 + (lane>>2);
        #pragma unroll
        for (int nf = 0; nf < 8; nf++) {
            const int n0 = bn + wn + nf*8 + 2*(lane&3);
            const float2 bv = *(const float2*)(bias + n0);
            const float r00 = acc[mf][nf][0] + bv.x, r01 = acc[mf][nf][1] + bv.y;
            const float r10 = acc[mf][nf][2] + bv.x, r11 = acc[mf][nf][3] + bv.y;
            if (OUT_HALF) {
                *(__half2*)(Ch + (size_t)m0 * DMODEL + n0) =
                    __floats2half2_rn(r00, r01);
                *(__half2*)(Ch + (size_t)(m0+8) * DMODEL + n0) =
                    __floats2half2_rn(r10, r11);
            } else {
                *(float2*)(Cf + (size_t)m0 * DMODEL + n0)     = make_float2(r00, r01);
                *(float2*)(Cf + (size_t)(m0+8) * DMODEL + n0) = make_float2(r10, r11);
            }
        }
    }
}

__global__ __launch_bounds__(128, 2) void gemm_out(
    const __half* __restrict__ A, const __half* __restrict__ W,
    const float* __restrict__ bias, float* __restrict__ C)
{
    extern __shared__ __align__(16) char smg[];
    gemm_body<0>(A, W, bias, C, nullptr, smg);
}

__global__ __launch_bounds__(128, 2) void gemm_qkv(
    const float* __restrict__ bq, const float* __restrict__ bk,
    const float* __restrict__ bv)
{
    extern __shared__ __align__(16) char smg[];
    const __half* A; const __half* W; const float* bias; __half* C;
    if (blockIdx.z == 0)      { A = g_qh; W = g_Wqh; bias = bq; C = g_qw; }
    else if (blockIdx.z == 1) { A = g_kh; W = g_Wkh; bias = bk; C = g_kw; }
    else                      { A = g_vh; W = g_Wvh; bias = bv; C = g_vw; }
    gemm_body<1>(A, W, bias, nullptr, C, smg);
}

// ---------------------------------------------------------------------------
// Flash attention, fp16 mma + ldmatrix, FA2-style: P stays in registers
// (A-fragment of PV mma == packed S accumulator fragments; no smem round
// trip). K/V double-buffered cp.async. scale = 1/32 in the exponent.
// ---------------------------------------------------------------------------
#define FPH 72    /* halfs */
#define KVB (64*FPH*2)   /* 9216 bytes per K or V buffer */

__global__ __launch_bounds__(256, 2) void flash_mma(
    const __half* __restrict__ Q, const __half* __restrict__ K,
    const __half* __restrict__ V, __half* __restrict__ O)
{
    extern __shared__ __align__(16) char smf[];
    __half* Qs = (__half*)smf;              // [128][FPH]
    __half* Ks = Qs + 128*FPH;              // [2][64][FPH]
    __half* Vs = Ks + 2*64*FPH;             // [2][64][FPH] row-major (j, d)
    const unsigned sQ = (unsigned)__cvta_generic_to_shared(Qs);
    const unsigned sK = (unsigned)__cvta_generic_to_shared(Ks);
    const unsigned sV = (unsigned)__cvta_generic_to_shared(Vs);

    const int qt = gridDim.x - 1 - blockIdx.x;   // big tiles first
    const int h  = blockIdx.y;
    const int b  = blockIdx.z;
    const int tid  = threadIdx.x;
    const int lane = tid & 31;
    const int wid  = tid >> 5;
    const int qBase = qt * 128;

    const __half* Qg  = Q + ((size_t)b * SEQ + qBase) * DMODEL + h * DHEAD;
    const __half* Kg0 = K + ((size_t)b * SEQ) * DMODEL + h * DHEAD;
    const __half* Vg0 = V + ((size_t)b * SEQ) * DMODEL + h * DHEAD;

    // Stage Q: 128 rows x 64 halfs = 1024 16B-chunks, 4 per thread
    #pragma unroll
    for (int i = 0; i < 4; i++) {
        const int idx = i*256 + tid;
        const int row = idx >> 3;
        const int c   = (idx & 7) * 8;
        cp16(Qs + row*FPH + c, Qg + (size_t)row*DMODEL + c);
    }

    auto stageKV = [&](int kBase, int buf) {
        #pragma unroll
        for (int i = 0; i < 2; i++) {
            const int idx = i*256 + tid;
            const int row = idx >> 3;
            const int c   = (idx & 7) * 8;
            cp16(Ks + buf*(64*FPH) + row*FPH + c,
                 Kg0 + (size_t)(kBase + row)*DMODEL + c);
            cp16(Vs + buf*(64*FPH) + row*FPH + c,
                 Vg0 + (size_t)(kBase + row)*DMODEL + c);
        }
        CP_COMMIT;
    };
    stageKV(0, 0);

    const int r0  = (wid << 4) + (lane >> 2);
    const int qi0 = qBase + r0;
    const int qi1 = qi0 + 8;

    // ldmatrix addressing
    const int g = lane >> 3, r = lane & 7;
    const unsigned qRow = sQ + (unsigned)((wid*16 + (g&1)*8 + r) * 144 + (g>>1)*16);
    const unsigned kRow = sK + (unsigned)(((g&1)*8 + r) * 144 + (g>>1)*16);
    const unsigned vRow = sV + (unsigned)(((g>>1)*8 + r) * 144 + (g&1)*16);

    float m0 = -1e30f, m1 = -1e30f, l0 = 0.0f, l1 = 0.0f;
    float o[8][4];
    #pragma unroll
    for (int nf = 0; nf < 8; nf++)
        #pragma unroll
        for (int e = 0; e < 4; e++) o[nf][e] = 0.0f;

    const float c2 = 0.03125f * 1.4426950408889634f;  // scale * log2(e)

    const int ktMax = 2*qt + 1;
    for (int kt = 0; kt <= ktMax; kt++) {
        const int cur = kt & 1;
        CP_WAIT0;                // K/V(kt) [+Q on kt=0] landed
        __syncthreads();         // all threads past iter kt-1 reads

        // Prefetch next K/V tile — overlaps with this tile's compute
        if (kt < ktMax) stageKV((kt + 1) * 64, cur ^ 1);

        const unsigned kb = kRow + cur*KVB;
        const unsigned vb = vRow + cur*KVB;
        const int kBase = kt * 64;

        // S = Q @ K^T (unscaled)
        float s[8][4];
        #pragma unroll
        for (int nf = 0; nf < 8; nf++)
            #pragma unroll
            for (int e = 0; e < 4; e++) s[nf][e] = 0.0f;

        #pragma unroll
        for (int ks = 0; ks < 4; ks++) {          // k16 steps over d=64
            unsigned a[4];
            ldsm4(a[0], a[1], a[2], a[3], qRow + ks*32);
            #pragma unroll
            for (int nf2 = 0; nf2 < 4; nf2++) {
                unsigned b0, b1, b2, b3;
                ldsm4(b0, b1, b2, b3, kb + nf2*16*144 + ks*32);
                mma16(s[nf2*2],   a, b0, b2);
                mma16(s[nf2*2+1], a, b1, b3);
            }
        }

        // Mask + online softmax
        const bool needMask = (kt >= 2*qt);
        float mt0 = -1e30f, mt1 = -1e30f;
        #pragma unroll
        for (int nf = 0; nf < 8; nf++) {
            #pragma unroll
            for (int e = 0; e < 2; e++) {
                if (needMask) {
                    const int kj = kBase + nf*8 + 2*(lane&3) + e;
                    if (kj > qi0) s[nf][e]   = -1e30f;
                    if (kj > qi1) s[nf][2+e] = -1e30f;
                }
                mt0 = fmaxf(mt0, s[nf][e]);
                mt1 = fmaxf(mt1, s[nf][2+e]);
            }
        }
        mt0 = fmaxf(mt0, __shfl_xor_sync(0xffffffffu, mt0, 1));
        mt0 = fmaxf(mt0, __shfl_xor_sync(0xffffffffu, mt0, 2));
        mt1 = fmaxf(mt1, __shfl_xor_sync(0xffffffffu, mt1, 1));
        mt1 = fmaxf(mt1, __shfl_xor_sync(0xffffffffu, mt1, 2));

        const float mn0 = fmaxf(m0, mt0);
        const float mn1 = fmaxf(m1, mt1);
        const float alpha0 = ex2((m0 - mn0) * c2);
        const float alpha1 = ex2((m1 - mn1) * c2);
        m0 = mn0; m1 = mn1;

        float ls0 = 0.0f, ls1 = 0.0f;
        #pragma unroll
        for (int nf = 0; nf < 8; nf++) {
            #pragma unroll
            for (int e = 0; e < 2; e++) {
                const float p0 = ex2((s[nf][e]   - mn0) * c2);
                const float p1 = ex2((s[nf][2+e] - mn1) * c2);
                s[nf][e]   = p0;
                s[nf][2+e] = p1;
                ls0 += p0; ls1 += p1;
            }
        }
        ls0 += __shfl_xor_sync(0xffffffffu, ls0, 1);
        ls0 += __shfl_xor_sync(0xffffffffu, ls0, 2);
        ls1 += __shfl_xor_sync(0xffffffffu, ls1, 1);
        ls1 += __shfl_xor_sync(0xffffffffu, ls1, 2);
        l0 = l0*alpha0 + ls0;
        l1 = l1*alpha1 + ls1;

        #pragma unroll
        for (int nf = 0; nf < 8; nf++) {
            o[nf][0] *= alpha0; o[nf][1] *= alpha0;
            o[nf][2] *= alpha1; o[nf][3] *= alpha1;
        }

        // O += P @ V — FA2 identity: P A-fragments are the packed S
        // accumulator fragments (two adjacent n8 tiles per k16 step).
        #pragma unroll
        for (int ks = 0; ks < 4; ks++) {          // k16 steps over j=64
            unsigned a[4];
            __half2 h0 = __floats2half2_rn(s[2*ks][0],   s[2*ks][1]);
            __half2 h1 = __floats2half2_rn(s[2*ks][2],   s[2*ks][3]);
            __half2 h2 = __floats2half2_rn(s[2*ks+1][0], s[2*ks+1][1]);
            __half2 h3 = __floats2half2_rn(s[2*ks+1][2], s[2*ks+1][3]);
            a[0] = *(unsigned*)&h0;
            a[1] = *(unsigned*)&h1;
            a[2] = *(unsigned*)&h2;
            a[3] = *(unsigned*)&h3;
            #pragma unroll
            for (int nf2 = 0; nf2 < 4; nf2++) {
                unsigned b0, b1, b2, b3;
                ldsm4t(b0, b1, b2, b3, vb + ks*16*144 + nf2*32);
                mma16(o[nf2*2],   a, b0, b2);
                mma16(o[nf2*2+1], a, b1, b3);
            }
        }
    }

    // Normalize + write fp16
    const float inv0 = 1.0f / l0;
    const float inv1 = 1.0f / l1;
    __half* Ob = O + (size_t)b * SEQ * DMODEL + (size_t)h * DHEAD;
    #pragma unroll
    for (int nf = 0; nf < 8; nf++) {
        const int n = nf*8 + 2*(lane&3);
        *(__half2*)(Ob + (size_t)qi0 * DMODEL + n) =
            __floats2half2_rn(o[nf][0]*inv0, o[nf][1]*inv0);
        *(__half2*)(Ob + (size_t)qi1 * DMODEL + n) =
            __floats2half2_rn(o[nf][2]*inv1, o[nf][3]*inv1);
    }
}

// ---------------------------------------------------------------------------
extern "C" void kernel_launch(void* const* d_in, const int* in_sizes, int n_in,
                              void* d_out, int out_size)
{
    const float* q  = (const float*)d_in[0];
    const float* k  = (const float*)d_in[1];
    const float* v  = (const float*)d_in[2];
    const float* Wq = (const float*)d_in[3];
    const float* bq = (const float*)d_in[4];
    const float* Wk = (const float*)d_in[5];
    const float* bk = (const float*)d_in[6];
    const float* Wv = (const float*)d_in[7];
    const float* bv = (const float*)d_in[8];
    const float* Wo = (const float*)d_in[9];
    const float* bo = (const float*)d_in[10];
    float* out = (float*)d_out;

    __half *qw, *kw, *vw, *att, *Woh;
    cudaGetSymbolAddress((void**)&qw,  g_qw);
    cudaGetSymbolAddress((void**)&kw,  g_kw);
    cudaGetSymbolAddress((void**)&vw,  g_vw);
    cudaGetSymbolAddress((void**)&att, g_att);
    cudaGetSymbolAddress((void**)&Woh, g_Woh);

    const int smemGemm  = 4 * ABYTES;                          // 73728
    const int smemFlash = (128*FPH + 2*64*FPH + 2*64*FPH) * 2; // 55296
    cudaFuncSetAttribute(gemm_qkv,
                         cudaFuncAttributeMaxDynamicSharedMemorySize, smemGemm);
    cudaFuncSetAttribute(gemm_out,
                         cudaFuncAttributeMaxDynamicSharedMemorySize, smemGemm);
    cudaFuncSetAttribute(flash_mma,
                         cudaFuncAttributeMaxDynamicSharedMemorySize, smemFlash);

    // 1) fp16 pre-round of inputs + weights
    pre_round<<<dim3(MROWS*DMODEL/(256*8), 7), 256>>>(q, k, v, Wq, Wk, Wv, Wo);

    // 2) fused QKV projections (fp16 out)
    dim3 gQKV(DMODEL/128, MROWS/128, 3);
    gemm_qkv<<<gQKV, 128, smemGemm>>>(bq, bk, bv);

    // 3) causal flash attention (fp16 out)
    flash_mma<<<dim3(SEQ/128, NHEAD, BATCH), 256, smemFlash>>>(qw, kw, vw, att);

    // 4) output projection (f32 out)
    dim3 gGemm(DMODEL/128, MROWS/128);
    gemm_out<<<gGemm, 128, smemGemm>>>(att, Woh, bo, out);
}

// round 16
// speedup vs baseline: 1.0033x; 1.0010x over previous
#include <cuda_runtime.h>
#include <cuda_fp16.h>
#include <math.h>

#define BATCH 2
#define SEQ 2048
#define DMODEL 1024
#define NHEAD 16
#define DHEAD 64
#define MROWS (BATCH*SEQ)   /* 4096 */

// Scratch (allocation-free) — all fp16
__device__ __half g_qh[MROWS*DMODEL];
__device__ __half g_kh[MROWS*DMODEL];
__device__ __half g_vh[MROWS*DMODEL];
__device__ __half g_Wqh[DMODEL*DMODEL];
__device__ __half g_Wkh[DMODEL*DMODEL];
__device__ __half g_Wvh[DMODEL*DMODEL];
__device__ __half g_Woh[DMODEL*DMODEL];
__device__ __half g_qw[MROWS*DMODEL];
__device__ __half g_kw[MROWS*DMODEL];
__device__ __half g_vw[MROWS*DMODEL];
__device__ __half g_att[MROWS*DMODEL];

// ---------------------------------------------------------------------------
// Helpers
// ---------------------------------------------------------------------------
__device__ __forceinline__ float ex2(float x) {
    float r;
    asm("ex2.approx.f32 %0, %1;" : "=f"(r) : "f"(x));
    return r;
}

__device__ __forceinline__ void mma16(float* d, const unsigned* a,
                                      unsigned b0, unsigned b1) {
    asm volatile(
        "mma.sync.aligned.m16n8k16.row.col.f32.f16.f16.f32 "
        "{%0,%1,%2,%3}, {%4,%5,%6,%7}, {%8,%9}, {%0,%1,%2,%3};"
        : "+f"(d[0]), "+f"(d[1]), "+f"(d[2]), "+f"(d[3])
        : "r"(a[0]), "r"(a[1]), "r"(a[2]), "r"(a[3]), "r"(b0), "r"(b1));
}

__device__ __forceinline__ void ldsm4(unsigned& r0, unsigned& r1,
                                      unsigned& r2, unsigned& r3, unsigned a) {
    asm volatile("ldmatrix.sync.aligned.m8n8.x4.shared.b16 {%0,%1,%2,%3}, [%4];"
        : "=r"(r0), "=r"(r1), "=r"(r2), "=r"(r3) : "r"(a));
}
__device__ __forceinline__ void ldsm4t(unsigned& r0, unsigned& r1,
                                       unsigned& r2, unsigned& r3, unsigned a) {
    asm volatile("ldmatrix.sync.aligned.m8n8.x4.trans.shared.b16 {%0,%1,%2,%3}, [%4];"
        : "=r"(r0), "=r"(r1), "=r"(r2), "=r"(r3) : "r"(a));
}

__device__ __forceinline__ void cp16(const void* smem_dst, const void* gsrc) {
    unsigned d = (unsigned)__cvta_generic_to_shared(smem_dst);
    asm volatile("cp.async.cg.shared.global [%0], [%1], 16;" :: "r"(d), "l"(gsrc));
}
#define CP_COMMIT asm volatile("cp.async.commit_group;")
#define CP_WAIT0  asm volatile("cp.async.wait_group 0;")
#define CP_WAIT1  asm volatile("cp.async.wait_group 1;")

// ---------------------------------------------------------------------------
// Pre-round: f32 -> fp16 copies. blockIdx.y selects tensor.
// ---------------------------------------------------------------------------
__global__ __launch_bounds__(256) void pre_round(
    const float* __restrict__ q, const float* __restrict__ k,
    const float* __restrict__ v,
    const float* __restrict__ Wq, const float* __restrict__ Wk,
    const float* __restrict__ Wv, const float* __restrict__ Wo)
{
    const float* src; __half* dst; int n;
    switch (blockIdx.y) {
        case 0: src = q;  dst = g_qh;  n = MROWS*DMODEL;  break;
        case 1: src = k;  dst = g_kh;  n = MROWS*DMODEL;  break;
        case 2: src = v;  dst = g_vh;  n = MROWS*DMODEL;  break;
        case 3: src = Wq; dst = g_Wqh; n = DMODEL*DMODEL; break;
        case 4: src = Wk; dst = g_Wkh; n = DMODEL*DMODEL; break;
        case 5: src = Wv; dst = g_Wvh; n = DMODEL*DMODEL; break;
        default: src = Wo; dst = g_Woh; n = DMODEL*DMODEL; break;
    }
    const int idx = (blockIdx.x * 256 + threadIdx.x) * 8;
    if (idx < n) {
        float4 a = *(const float4*)(src + idx);
        float4 b = *(const float4*)(src + idx + 4);
        __half2 h[4];
        h[0] = __floats2half2_rn(a.x, a.y);
        h[1] = __floats2half2_rn(a.z, a.w);
        h[2] = __floats2half2_rn(b.x, b.y);
        h[3] = __floats2half2_rn(b.z, b.w);
        *(uint4*)(dst + idx) = *(uint4*)h;
    }
}

// ---------------------------------------------------------------------------
// GEMM: C[m,n] = sum_k A[m,k]*W[n,k] + bias[n], fp16 operands, f32 accum.
// CTA 128x128, BK=64 double-buffered cp.async, 4 warps (2x2) of 64x64.
// Pitch 72 halfs (144B) -> conflict-free LDSM.
// ---------------------------------------------------------------------------
#define APITCH 72                 /* halfs */
#define ABYTES (128*APITCH*2)     /* 18432 per buffer */

template<int OUT_HALF>
__device__ __forceinline__ void gemm_body(
    const __half* __restrict__ A, const __half* __restrict__ W,
    const float* __restrict__ bias, float* __restrict__ Cf,
    __half* __restrict__ Ch, char* smem)
{
    __half* Asm = (__half*)smem;                  // [2][128*APITCH]
    __half* Wsm = (__half*)(smem + 2*ABYTES);
    const unsigned sA = (unsigned)__cvta_generic_to_shared(Asm);
    const unsigned sW = (unsigned)__cvta_generic_to_shared(Wsm);

    const int tid  = threadIdx.x;
    const int lane = tid & 31;
    const int wid  = tid >> 5;           // 0..3
    const int bm = blockIdx.y * 128;
    const int bn = blockIdx.x * 128;
    const int wm = (wid & 1) * 64;
    const int wn = (wid >> 1) * 64;

    const __half* Ag = A + (size_t)bm * DMODEL;
    const __half* Wg = W + (size_t)bn * DMODEL;

    float acc[4][8][4];
    #pragma unroll
    for (int mf = 0; mf < 4; mf++)
        #pragma unroll
        for (int nf = 0; nf < 8; nf++)
            #pragma unroll
            for (int e = 0; e < 4; e++) acc[mf][nf][e] = 0.0f;

    auto stage = [&](int buf, int k0) {
        #pragma unroll
        for (int i = 0; i < 8; i++) {
            const int idx = i*128 + tid;
            const int row = idx >> 3;
            const int c   = (idx & 7) * 8;
            cp16(Asm + buf*(128*APITCH) + row*APITCH + c,
                 Ag + (size_t)row*DMODEL + k0 + c);
            cp16(Wsm + buf*(128*APITCH) + row*APITCH + c,
                 Wg + (size_t)row*DMODEL + k0 + c);
        }
        CP_COMMIT;
    };

    stage(0, 0);

    // ldmatrix lane addressing (g = lane>>3 selects sub-matrix)
    const int g = lane >> 3, r = lane & 7;
    const unsigned aBase = sA + (unsigned)((wm + (g&1)*8 + r) * 144 + (g>>1)*16);
    const unsigned wBase = sW + (unsigned)((wn + (g&1)*8 + r) * 144 + (g>>1)*16);

    const int ntiles = DMODEL / 64;      // 16
    for (int kt = 0; kt < ntiles; kt++) {
        const int cur = kt & 1;
        if (kt + 1 < ntiles) {
            stage(cur ^ 1, (kt + 1) * 64);
            CP_WAIT1;
        } else {
            CP_WAIT0;
        }
        __syncthreads();

        const unsigned ab = aBase + cur*ABYTES;
        const unsigned wb = wBase + cur*ABYTES;
        #pragma unroll
        for (int s = 0; s < 4; s++) {                 // 4 k16-steps
            unsigned af[4][4];
            #pragma unroll
            for (int mf = 0; mf < 4; mf++)
                ldsm4(af[mf][0], af[mf][1], af[mf][2], af[mf][3],
                      ab + mf*16*144 + s*32);
            #pragma unroll
            for (int nf2 = 0; nf2 < 4; nf2++) {
                unsigned b0, b1, b2, b3;
                ldsm4(b0, b1, b2, b3, wb + nf2*16*144 + s*32);
                #pragma unroll
                for (int mf = 0; mf < 4; mf++) {
                    mma16(acc[mf][nf2*2],   af[mf], b0, b2);
                    mma16(acc[mf][nf2*2+1], af[mf], b1, b3);
                }
            }
        }
        __syncthreads();
    }

    // Epilogue
    #pragma unroll
    for (int mf = 0; mf < 4; mf++) {
        const int m0 = bm + wm + mf*16 + (lane>>2);
        #pragma unroll
        for (int nf = 0; nf < 8; nf++) {
            const int n0 = bn + wn + nf*8 + 2*(lane&3);
            const float2 bv = *(const float2*)(bias + n0);
            const float r00 = acc[mf][nf][0] + bv.x, r01 = acc[mf][nf][1] + bv.y;
            const float r10 = acc[mf][nf][2] + bv.x, r11 = acc[mf][nf][3] + bv.y;
            if (OUT_HALF) {
                *(__half2*)(Ch + (size_t)m0 * DMODEL + n0) =
                    __floats2half2_rn(r00, r01);
                *(__half2*)(Ch + (size_t)(m0+8) * DMODEL + n0) =
                    __floats2half2_rn(r10, r11);
            } else {
                *(float2*)(Cf + (size_t)m0 * DMODEL + n0)     = make_float2(r00, r01);
                *(float2*)(Cf + (size_t)(m0+8) * DMODEL + n0) = make_float2(r10, r11);
            }
        }
    }
}

__global__ __launch_bounds__(128, 2) void gemm_out(
    const __half* __restrict__ A, const __half* __restrict__ W,
    const float* __restrict__ bias, float* __restrict__ C)
{
    extern __shared__ __align__(16) char smg[];
    gemm_body<0>(A, W, bias, C, nullptr, smg);
}

__global__ __launch_bounds__(128, 2) void gemm_qkv(
    const float* __restrict__ bq, const float* __restrict__ bk,
    const float* __restrict__ bv)
{
    extern __shared__ __align__(16) char smg[];
    const __half* A; const __half* W; const float* bias; __half* C;
    if (blockIdx.z == 0)      { A = g_qh; W = g_Wqh; bias = bq; C = g_qw; }
    else if (blockIdx.z == 1) { A = g_kh; W = g_Wkh; bias = bk; C = g_kw; }
    else                      { A = g_vh; W = g_Wvh; bias = bv; C = g_vw; }
    gemm_body<1>(A, W, bias, nullptr, C, smg);
}

// ---------------------------------------------------------------------------
// Flash attention, fp16 mma + ldmatrix, FA2-style: P stays in registers
// (A-fragment of PV mma == packed S accumulator fragments; no smem round
// trip). K/V double-buffered cp.async. scale = 1/32 in the exponent.
// ---------------------------------------------------------------------------
#define FPH 72    /* halfs */
#define KVB (64*FPH*2)   /* 9216 bytes per K or V buffer */

__global__ __launch_bounds__(256, 2) void flash_mma(
    const __half* __restrict__ Q, const __half* __restrict__ K,
    const __half* __restrict__ V, __half* __restrict__ O)
{
    extern __shared__ __align__(16) char smf[];
    __half* Qs = (__half*)smf;              // [128][FPH]
    __half* Ks = Qs + 128*FPH;              // [2][64][FPH]
    __half* Vs = Ks + 2*64*FPH;             // [2][64][FPH] row-major (j, d)
    const unsigned sQ = (unsigned)__cvta_generic_to_shared(Qs);
    const unsigned sK = (unsigned)__cvta_generic_to_shared(Ks);
    const unsigned sV = (unsigned)__cvta_generic_to_shared(Vs);

    const int qt = gridDim.x - 1 - blockIdx.x;   // big tiles first
    const int h  = blockIdx.y;
    const int b  = blockIdx.z;
    const int tid  = threadIdx.x;
    const int lane = tid & 31;
    const int wid  = tid >> 5;
    const int qBase = qt * 128;

    const __half* Qg  = Q + ((size_t)b * SEQ + qBase) * DMODEL + h * DHEAD;
    const __half* Kg0 = K + ((size_t)b * SEQ) * DMODEL + h * DHEAD;
    const __half* Vg0 = V + ((size_t)b * SEQ) * DMODEL + h * DHEAD;

    // Stage Q: 128 rows x 64 halfs = 1024 16B-chunks, 4 per thread
    #pragma unroll
    for (int i = 0; i < 4; i++) {
        const int idx = i*256 + tid;
        const int row = idx >> 3;
        const int c   = (idx & 7) * 8;
        cp16(Qs + row*FPH + c, Qg + (size_t)row*DMODEL + c);
    }

    auto stageKV = [&](int kBase, int buf) {
        #pragma unroll
        for (int i = 0; i < 2; i++) {
            const int idx = i*256 + tid;
            const int row = idx >> 3;
            const int c   = (idx & 7) * 8;
            cp16(Ks + buf*(64*FPH) + row*FPH + c,
                 Kg0 + (size_t)(kBase + row)*DMODEL + c);
            cp16(Vs + buf*(64*FPH) + row*FPH + c,
                 Vg0 + (size_t)(kBase + row)*DMODEL + c);
        }
        CP_COMMIT;
    };
    stageKV(0, 0);

    const int r0  = (wid << 4) + (lane >> 2);
    const int qi0 = qBase + r0;
    const int qi1 = qi0 + 8;

    // ldmatrix addressing
    const int g = lane >> 3, r = lane & 7;
    const unsigned qRow = sQ + (unsigned)((wid*16 + (g&1)*8 + r) * 144 + (g>>1)*16);
    const unsigned kRow = sK + (unsigned)(((g&1)*8 + r) * 144 + (g>>1)*16);
    const unsigned vRow = sV + (unsigned)(((g>>1)*8 + r) * 144 + (g&1)*16);

    float m0 = -1e30f, m1 = -1e30f, l0 = 0.0f, l1 = 0.0f;
    float o[8][4];
    #pragma unroll
    for (int nf = 0; nf < 8; nf++)
        #pragma unroll
        for (int e = 0; e < 4; e++) o[nf][e] = 0.0f;

    const float c2 = 0.03125f * 1.4426950408889634f;  // scale * log2(e)

    const int ktMax = 2*qt + 1;
    for (int kt = 0; kt <= ktMax; kt++) {
        const int cur = kt & 1;
        CP_WAIT0;                // K/V(kt) [+Q on kt=0] landed
        __syncthreads();         // all threads past iter kt-1 reads

        // Prefetch next K/V tile — overlaps with this tile's compute
        if (kt < ktMax) stageKV((kt + 1) * 64, cur ^ 1);

        const unsigned kb = kRow + cur*KVB;
        const unsigned vb = vRow + cur*KVB;
        const int kBase = kt * 64;

        // S = Q @ K^T (unscaled)
        float s[8][4];
        #pragma unroll
        for (int nf = 0; nf < 8; nf++)
            #pragma unroll
            for (int e = 0; e < 4; e++) s[nf][e] = 0.0f;

        #pragma unroll
        for (int ks = 0; ks < 4; ks++) {          // k16 steps over d=64
            unsigned a[4];
            ldsm4(a[0], a[1], a[2], a[3], qRow + ks*32);
            #pragma unroll
            for (int nf2 = 0; nf2 < 4; nf2++) {
                unsigned b0, b1, b2, b3;
                ldsm4(b0, b1, b2, b3, kb + nf2*16*144 + ks*32);
                mma16(s[nf2*2],   a, b0, b2);
                mma16(s[nf2*2+1], a, b1, b3);
            }
        }

        // Mask + online softmax
        const bool needMask = (kt >= 2*qt);
        float mt0 = -1e30f, mt1 = -1e30f;
        #pragma unroll
        for (int nf = 0; nf < 8; nf++) {
            #pragma unroll
            for (int e = 0; e < 2; e++) {
                if (needMask) {
                    const int kj = kBase + nf*8 + 2*(lane&3) + e;
                    if (kj > qi0) s[nf][e]   = -1e30f;
                    if (kj > qi1) s[nf][2+e] = -1e30f;
                }
                mt0 = fmaxf(mt0, s[nf][e]);
                mt1 = fmaxf(mt1, s[nf][2+e]);
            }
        }
        mt0 = fmaxf(mt0, __shfl_xor_sync(0xffffffffu, mt0, 1));
        mt0 = fmaxf(mt0, __shfl_xor_sync(0xffffffffu, mt0, 2));
        mt1 = fmaxf(mt1, __shfl_xor_sync(0xffffffffu, mt1, 1));
        mt1 = fmaxf(mt1, __shfl_xor_sync(0xffffffffu, mt1, 2));

        const float mn0 = fmaxf(m0, mt0);
        const float mn1 = fmaxf(m1, mt1);
        const float alpha0 = ex2((m0 - mn0) * c2);
        const float alpha1 = ex2((m1 - mn1) * c2);
        m0 = mn0; m1 = mn1;

        float ls0 = 0.0f, ls1 = 0.0f;
        #pragma unroll
        for (int nf = 0; nf < 8; nf++) {
            #pragma unroll
            for (int e = 0; e < 2; e++) {
                const float p0 = ex2((s[nf][e]   - mn0) * c2);
                const float p1 = ex2((s[nf][2+e] - mn1) * c2);
                s[nf][e]   = p0;
                s[nf][2+e] = p1;
                ls0 += p0; ls1 += p1;
            }
        }
        ls0 += __shfl_xor_sync(0xffffffffu, ls0, 1);
        ls0 += __shfl_xor_sync(0xffffffffu, ls0, 2);
        ls1 += __shfl_xor_sync(0xffffffffu, ls1, 1);
        ls1 += __shfl_xor_sync(0xffffffffu, ls1, 2);
        l0 = l0*alpha0 + ls0;
        l1 = l1*alpha1 + ls1;

        #pragma unroll
        for (int nf = 0; nf < 8; nf++) {
            o[nf][0] *= alpha0; o[nf][1] *= alpha0;
            o[nf][2] *= alpha1; o[nf][3] *= alpha1;
        }

        // O += P @ V — FA2 identity: P A-fragments are the packed S
        // accumulator fragments (two adjacent n8 tiles per k16 step).
        #pragma unroll
        for (int ks = 0; ks < 4; ks++) {          // k16 steps over j=64
            unsigned a[4];
            __half2 h0 = __floats2half2_rn(s[2*ks][0],   s[2*ks][1]);
            __half2 h1 = __floats2half2_rn(s[2*ks][2],   s[2*ks][3]);
            __half2 h2 = __floats2half2_rn(s[2*ks+1][0], s[2*ks+1][1]);
            __half2 h3 = __floats2half2_rn(s[2*ks+1][2], s[2*ks+1][3]);
            a[0] = *(unsigned*)&h0;
            a[1] = *(unsigned*)&h1;
            a[2] = *(unsigned*)&h2;
            a[3] = *(unsigned*)&h3;
            #pragma unroll
            for (int nf2 = 0; nf2 < 4; nf2++) {
                unsigned b0, b1, b2, b3;
                ldsm4t(b0, b1, b2, b3, vb + ks*16*144 + nf2*32);
                mma16(o[nf2*2],   a, b0, b2);
                mma16(o[nf2*2+1], a, b1, b3);
            }
        }
    }

    // Normalize + write fp16
    const float inv0 = 1.0f / l0;
    const float inv1 = 1.0f / l1;
    __half* Ob = O + (size_t)b * SEQ * DMODEL + (size_t)h * DHEAD;
    #pragma unroll
    for (int nf = 0; nf < 8; nf++) {
        const int n = nf*8 + 2*(lane&3);
        *(__half2*)(Ob + (size_t)qi0 * DMODEL + n) =
            __floats2half2_rn(o[nf][0]*inv0, o[nf][1]*inv0);
        *(__half2*)(Ob + (size_t)qi1 * DMODEL + n) =
            __floats2half2_rn(o[nf][2]*inv1, o[nf][3]*inv1);
    }
}

// ---------------------------------------------------------------------------
extern "C" void kernel_launch(void* const* d_in, const int* in_sizes, int n_in,
                              void* d_out, int out_size)
{
    const float* q  = (const float*)d_in[0];
    const float* k  = (const float*)d_in[1];
    const float* v  = (const float*)d_in[2];
    const float* Wq = (const float*)d_in[3];
    const float* bq = (const float*)d_in[4];
    const float* Wk = (const float*)d_in[5];
    const float* bk = (const float*)d_in[6];
    const float* Wv = (const float*)d_in[7];
    const float* bv = (const float*)d_in[8];
    const float* Wo = (const float*)d_in[9];
    const float* bo = (const float*)d_in[10];
    float* out = (float*)d_out;

    __half *qw, *kw, *vw, *att, *Woh;
    cudaGetSymbolAddress((void**)&qw,  g_qw);
    cudaGetSymbolAddress((void**)&kw,  g_kw);
    cudaGetSymbolAddress((void**)&vw,  g_vw);
    cudaGetSymbolAddress((void**)&att, g_att);
    cudaGetSymbolAddress((void**)&Woh, g_Woh);

    const int smemGemm  = 4 * ABYTES;                          // 73728
    const int smemFlash = (128*FPH + 2*64*FPH + 2*64*FPH) * 2; // 55296
    cudaFuncSetAttribute(gemm_qkv,
                         cudaFuncAttributeMaxDynamicSharedMemorySize, smemGemm);
    cudaFuncSetAttribute(gemm_out,
                         cudaFuncAttributeMaxDynamicSharedMemorySize, smemGemm);
    cudaFuncSetAttribute(flash_mma,
                         cudaFuncAttributeMaxDynamicSharedMemorySize, smemFlash);

    // 1) fp16 pre-round of inputs + weights
    pre_round<<<dim3(MROWS*DMODEL/(256*8), 7), 256>>>(q, k, v, Wq, Wk, Wv, Wo);

    // 2) fused QKV projections (fp16 out)
    dim3 gQKV(DMODEL/128, MROWS/128, 3);
    gemm_qkv<<<gQKV, 128, smemGemm>>>(bq, bk, bv);

    // 3) causal flash attention (fp16 out)
    flash_mma<<<dim3(SEQ/128, NHEAD, BATCH), 256, smemFlash>>>(qw, kw, vw, att);

    // 4) output projection (f32 out)
    dim3 gGemm(DMODEL/128, MROWS/128);
    gemm_out<<<gGemm, 128, smemGemm>>>(att, Woh, bo, out);
}